// round 6
// baseline (speedup 1.0000x reference)
#include <cuda_runtime.h>
#include <math.h>

#define Bs   16
#define Cc   256
#define Hh   128
#define Ww   128
#define HW   16384
#define CHUNK 2          // batches per L2-blocked chunk (32MB scratch -> L2-resident)
#define PIX  32          // pixels per scatter block
#define SS   258         // smem row stride (words): even -> 8B-aligned LDS.64
#define EPSV 1e-05f

// Transposed accumulator scratch [CHUNK][HW][C] (32 MB, L2-resident; same
// addresses reused every chunk). g_att is FULL size [Bs][HW]: each k_div block
// uniquely owns 32 entries -> read at start, zero after tail barrier (no
// cross-block race). Both zero-initialized at load; k_div restores zeros after
// consumption, so every graph replay starts from zeroed state (deterministic).
__device__ float g_feat[(size_t)CHUNK * HW * Cc];
__device__ float g_att[(size_t)Bs * HW];

// -------------------------------------------- fused conv + scatter
__global__ __launch_bounds__(256) void k_scatter(
    const float* __restrict__ x, const float* __restrict__ cw,
    const float* __restrict__ cb, float* __restrict__ offo, int b0) {
    __shared__ float s_x[PIX * SS];     // 33 KB tile, [pixel][channel]
    __shared__ float s_w[3 * Cc];
    __shared__ float s_red[3 * 8 * 32];
    __shared__ float s_att[PIX];
    __shared__ int   s_idx[PIX];

    const int tid  = threadIdx.x;
    const int lane = tid & 31;
    const int warp = tid >> 5;
    const int bl   = blockIdx.y;        // local batch (scratch index)
    const int b    = b0 + bl;           // global batch
    const int hw0  = blockIdx.x * PIX;

    for (int i = tid; i < 3 * Cc; i += 256) s_w[i] = cw[i];
    __syncthreads();

    const float* xb = x + (size_t)b * Cc * HW + hw0;
    float a0 = 0.f, a1 = 0.f, a2 = 0.f;
#pragma unroll
    for (int k = 0; k < Cc / 8; k++) {
        int c = k * 8 + warp;                        // warp owns channel slice
        float v = __ldg(xb + (size_t)c * HW + lane); // coalesced over 32 pixels
        s_x[lane * SS + c] = v;
        a0 = fmaf(v, s_w[c],          a0);
        a1 = fmaf(v, s_w[Cc + c],     a1);
        a2 = fmaf(v, s_w[2 * Cc + c], a2);
    }
    s_red[(0 * 8 + warp) * 32 + lane] = a0;
    s_red[(1 * 8 + warp) * 32 + lane] = a1;
    s_red[(2 * 8 + warp) * 32 + lane] = a2;
    __syncthreads();

    if (warp == 0) {                    // lane == pixel within tile
        float r0 = cb[0], r1 = cb[1], r2 = cb[2];
#pragma unroll
        for (int w = 0; w < 8; w++) {
            r0 += s_red[w * 32 + lane];
            r1 += s_red[(8 + w) * 32 + lane];
            r2 += s_red[(16 + w) * 32 + lane];
        }
        float offy = r0 * (float)Hh;
        float offx = r1 * (float)Ww;
        float att  = expf(r2);
        int hw = hw0 + lane;
        int hh = hw >> 7, wc = hw & 127;
        // round-half-even (rintf) then clip, matching jnp.round + clip
        int iy = (int)fminf(fmaxf(rintf((float)hh + offy), 0.f), 127.f);
        int ix = (int)fminf(fmaxf(rintf((float)wc + offx), 0.f), 127.f);
        int idx = (iy << 7) + ix;
        s_att[lane] = att;
        s_idx[lane] = idx;
        size_t ob = (size_t)b * 2 * HW + hw;       // offset: [B][2][H][W]
        offo[ob]      = offy;
        offo[ob + HW] = offx;
        atomicAdd(&g_att[(size_t)b * HW + idx], att);
    }
    __syncthreads();

    // Scatter: each warp handles 4 pixels; per pixel, 2 x red.v4 per lane
    // covering a contiguous 1KB destination row g_feat[bl][idx][:].
#pragma unroll
    for (int p = warp; p < PIX; p += 8) {
        float att = s_att[p];
        float* dst = g_feat + ((size_t)bl * HW + s_idx[p]) * Cc;
        const float* src = s_x + p * SS;
#pragma unroll
        for (int r = 0; r < 2; r++) {
            int c0 = r * 128 + 4 * lane;
            float2 u = *reinterpret_cast<const float2*>(src + c0);
            float2 v = *reinterpret_cast<const float2*>(src + c0 + 2);
            asm volatile(
                "red.global.add.v4.f32 [%0], {%1, %2, %3, %4};" ::
                "l"(dst + c0),
                "f"(u.x * att), "f"(u.y * att), "f"(v.x * att), "f"(v.y * att)
                : "memory");
        }
    }
}

// ----------------- normalize + transpose to [B][C][HW], register-only
// Block owns [bl][hw0..hw0+31][all 256 channels] (32 KB of g_feat) + the 32
// g_att entries. Per warp: channel quads cq = 8*warp..8*warp+7, all 32 hw.
// Lane L loads float4 (4 channels at hw0+L); 4-lane groups hold 4x4 squares,
// transposed in registers via 2 shfl.bfly stages; stores are 128B-coalesced
// per channel row. No smem, no mid-kernel barriers (MLP=8 on the L2-hit
// loads). Scratch zeroed at end (after consumption -> no pending-miss hazard),
// g_att zeroed after a single tail barrier.
__global__ __launch_bounds__(256) void k_div(float* __restrict__ out, int b0) {
    const int tid  = threadIdx.x;
    const int lane = tid & 31;
    const int warp = tid >> 5;
    const int r    = lane & 3;
    const int g2   = lane >> 2;
    const int bl   = blockIdx.y;
    const int b    = b0 + bl;
    const int hw0  = blockIdx.x * 32;

    const float inv = 1.0f / (g_att[(size_t)b * HW + hw0 + lane] + EPSV);

    float4* srcq = reinterpret_cast<float4*>(g_feat + ((size_t)bl * HW + hw0) * Cc);
    float4 v[8];
#pragma unroll
    for (int k = 0; k < 8; k++)                 // 8 independent L2-hit LDG.128
        v[k] = srcq[lane * (Cc / 4) + warp * 8 + k];

#pragma unroll
    for (int k = 0; k < 8; k++) {
        float4 t = v[k];
        t.x *= inv; t.y *= inv; t.z *= inv; t.w *= inv;
        // 4x4 transpose within the 4-lane group (rows=hw, cols=channel)
        float s0 = (r & 2) ? t.x : t.z;
        float s1 = (r & 2) ? t.y : t.w;
        s0 = __shfl_xor_sync(0xffffffffu, s0, 2);
        s1 = __shfl_xor_sync(0xffffffffu, s1, 2);
        if (r & 2) { t.x = s0; t.y = s1; } else { t.z = s0; t.w = s1; }
        s0 = (r & 1) ? t.x : t.y;
        s1 = (r & 1) ? t.z : t.w;
        s0 = __shfl_xor_sync(0xffffffffu, s0, 1);
        s1 = __shfl_xor_sync(0xffffffffu, s1, 1);
        if (r & 1) { t.x = s0; t.z = s1; } else { t.y = s0; t.w = s1; }
        // lane now holds channel c = 4*(8*warp+k)+r at hw quad hw0+4*g2
        const int c = (warp * 8 + k) * 4 + r;
        *reinterpret_cast<float4*>(
            out + ((size_t)b * Cc + c) * HW + hw0 + 4 * g2) = t;
    }

    // Re-zero own scratch (loads above fully consumed -> stores ordered after)
    const float4 z = make_float4(0.f, 0.f, 0.f, 0.f);
#pragma unroll
    for (int k = 0; k < 8; k++)
        srcq[lane * (Cc / 4) + warp * 8 + k] = z;

    __syncthreads();                    // all warps' g_att reads done
    if (tid < 32)
        g_att[(size_t)b * HW + hw0 + tid] = 0.f;
}

// ---------------------------------------------------------------- launch
extern "C" void kernel_launch(void* const* d_in, const int* in_sizes, int n_in,
                              void* d_out, int out_size) {
    const float* x  = (const float*)d_in[0];   // [16,256,128,128]
    const float* cw = (const float*)d_in[1];   // [3,256]
    const float* cb = (const float*)d_in[2];   // [3]
    float* out  = (float*)d_out;                        // [B,C,HW]
    float* offo = out + (size_t)Bs * Cc * HW;           // [B,2,H,W]

    for (int b0 = 0; b0 < Bs; b0 += CHUNK) {
        k_scatter<<<dim3(HW / PIX, CHUNK), 256>>>(x, cw, cb, offo, b0);
        k_div<<<dim3(HW / 32, CHUNK), 256>>>(out, b0);
    }
}

// round 7
// speedup vs baseline: 1.2350x; 1.2350x over previous
#include <cuda_runtime.h>
#include <math.h>

#define Bs   16
#define Cc   256
#define Hh   128
#define Ww   128
#define HW   16384
#define CHUNK 2          // batches per L2-blocked chunk (32MB scratch -> L2-resident)
#define PIX  32          // pixels per scatter block
#define SS   258         // smem row stride (words): even -> 8B-aligned LDS.64
#define EPSV 1e-05f
#define TSTRIDE 1064     // words per transpose tile (32*33 + 8 pad)

// Transposed accumulator scratch [CHUNK][HW][C] (32 MB, L2-resident; same
// addresses reused every chunk). g_att full size [Bs][HW]: each k_div block
// uniquely owns 32 entries. Zero-initialized at load; k_div restores zeros
// after consumption (separate pass AFTER reads complete — R3 lesson: never
// store to a line with a pending same-thread load miss), so graph replays are
// deterministic.
__device__ float g_feat[(size_t)CHUNK * HW * Cc];
__device__ float g_att[(size_t)Bs * HW];

// Tiny prefetch kernel: warms cw/cb in L2 and shifts the ncu -s window so the
// next capture lands on k_scatter (diagnostics; negligible cost).
__global__ void k_pref(const float* __restrict__ cw, const float* __restrict__ cb) {
    float v = cw[threadIdx.x] + ((threadIdx.x < 3) ? cb[threadIdx.x] : 0.f);
    asm volatile("" :: "f"(v));
}

// -------------------------------------------- fused conv + scatter
__global__ __launch_bounds__(256) void k_scatter(
    const float* __restrict__ x, const float* __restrict__ cw,
    const float* __restrict__ cb, float* __restrict__ offo, int b0) {
    __shared__ float s_x[PIX * SS];     // 33 KB tile, [pixel][channel]
    __shared__ float s_w[3 * Cc];
    __shared__ float s_red[3 * 8 * 32];
    __shared__ float s_att[PIX];
    __shared__ int   s_idx[PIX];

    const int tid  = threadIdx.x;
    const int lane = tid & 31;
    const int warp = tid >> 5;
    const int bl   = blockIdx.y;        // local batch (scratch index)
    const int b    = b0 + bl;           // global batch
    const int hw0  = blockIdx.x * PIX;

    for (int i = tid; i < 3 * Cc; i += 256) s_w[i] = cw[i];
    __syncthreads();

    const float* xb = x + (size_t)b * Cc * HW + hw0;
    float a0 = 0.f, a1 = 0.f, a2 = 0.f;
#pragma unroll
    for (int k = 0; k < Cc / 8; k++) {
        int c = k * 8 + warp;                        // warp owns channel slice
        float v = __ldg(xb + (size_t)c * HW + lane); // coalesced over 32 pixels
        s_x[lane * SS + c] = v;
        a0 = fmaf(v, s_w[c],          a0);
        a1 = fmaf(v, s_w[Cc + c],     a1);
        a2 = fmaf(v, s_w[2 * Cc + c], a2);
    }
    s_red[(0 * 8 + warp) * 32 + lane] = a0;
    s_red[(1 * 8 + warp) * 32 + lane] = a1;
    s_red[(2 * 8 + warp) * 32 + lane] = a2;
    __syncthreads();

    if (warp == 0) {                    // lane == pixel within tile
        float r0 = cb[0], r1 = cb[1], r2 = cb[2];
#pragma unroll
        for (int w = 0; w < 8; w++) {
            r0 += s_red[w * 32 + lane];
            r1 += s_red[(8 + w) * 32 + lane];
            r2 += s_red[(16 + w) * 32 + lane];
        }
        float offy = r0 * (float)Hh;
        float offx = r1 * (float)Ww;
        float att  = expf(r2);
        int hw = hw0 + lane;
        int hh = hw >> 7, wc = hw & 127;
        // round-half-even (rintf) then clip, matching jnp.round + clip
        int iy = (int)fminf(fmaxf(rintf((float)hh + offy), 0.f), 127.f);
        int ix = (int)fminf(fmaxf(rintf((float)wc + offx), 0.f), 127.f);
        int idx = (iy << 7) + ix;
        s_att[lane] = att;
        s_idx[lane] = idx;
        size_t ob = (size_t)b * 2 * HW + hw;       // offset: [B][2][H][W]
        offo[ob]      = offy;
        offo[ob + HW] = offx;
        atomicAdd(&g_att[(size_t)b * HW + idx], att);
    }
    __syncthreads();

    // Scatter: each warp handles 4 pixels; per pixel, 2 x red.v4 per lane
    // covering a contiguous 1KB destination row g_feat[bl][idx][:].
#pragma unroll
    for (int p = warp; p < PIX; p += 8) {
        float att = s_att[p];
        float* dst = g_feat + ((size_t)bl * HW + s_idx[p]) * Cc;
        const float* src = s_x + p * SS;
#pragma unroll
        for (int r = 0; r < 2; r++) {
            int c0 = r * 128 + 4 * lane;
            float2 u = *reinterpret_cast<const float2*>(src + c0);
            float2 v = *reinterpret_cast<const float2*>(src + c0 + 2);
            asm volatile(
                "red.global.add.v4.f32 [%0], {%1, %2, %3, %4};" ::
                "l"(dst + c0),
                "f"(u.x * att), "f"(u.y * att), "f"(v.x * att), "f"(v.y * att)
                : "memory");
        }
    }
}

// ----------------- normalize + transpose to [B][C][HW] + re-zero scratch
// Load phase (R5-proven): 8 independent coalesced LDG.128 per thread (MLP=8)
// into 8 padded 32x33 smem tiles; ONE barrier. Store phase: warp w owns
// channel group w; lane (q=l>>2, jl=l&3) gathers 4 hw values per channel
// (conflict-free: bank = 4q + jl + i + 4*it mod 32) and writes STG.128
// (512 global stores/block instead of 2048). inv applied per hw component.
__global__ __launch_bounds__(256) void k_div(float* __restrict__ out, int b0) {
    __shared__ float t[8 * TSTRIDE];    // ~34 KB
    __shared__ float inv[32];
    const int tid = threadIdx.x;
    const int bl  = blockIdx.y;
    const int b   = b0 + bl;
    const int hw0 = blockIdx.x * 32;

    if (tid < 32)
        inv[tid] = 1.0f / (g_att[(size_t)b * HW + hw0 + tid] + EPSV);

    const float4* src = reinterpret_cast<const float4*>(
        g_feat + ((size_t)bl * HW + hw0) * Cc);
#pragma unroll
    for (int k = 0; k < 8; k++) {
        int i  = tid + k * 256;         // [0, 2048)
        int hw = i >> 6;                // 0..31 (pixel)
        int cq = i & 63;                // float4 index within 256 channels
        float4 v = src[i];
        int g  = cq >> 3;               // channel group (tile)
        int cc = (cq & 7) * 4;          // channel within tile
        float* d = &t[g * TSTRIDE + hw * 33 + cc];
        d[0] = v.x; d[1] = v.y; d[2] = v.z; d[3] = v.w;
    }
    __syncthreads();

    const int lane = tid & 31;
    const int g    = tid >> 5;          // warp -> channel group
    const int q    = lane >> 2;         // hw quad (4q..4q+3)
    const int jl   = lane & 3;          // channel sub-lane
    const float4 iv = *reinterpret_cast<const float4*>(&inv[4 * q]); // broadcast-friendly
    const float* tg = &t[g * TSTRIDE];
#pragma unroll
    for (int it = 0; it < 8; it++) {
        const int cc = it * 4 + jl;     // channel within group
        float4 o;
        o.x = tg[(4 * q + 0) * 33 + cc] * iv.x;
        o.y = tg[(4 * q + 1) * 33 + cc] * iv.y;
        o.z = tg[(4 * q + 2) * 33 + cc] * iv.z;
        o.w = tg[(4 * q + 3) * 33 + cc] * iv.w;
        *reinterpret_cast<float4*>(
            out + ((size_t)b * Cc + g * 32 + cc) * HW + hw0 + 4 * q) = o;
    }

    // Re-zero this block's scratch region (all loads above completed).
    float4* fz = reinterpret_cast<float4*>(g_feat + ((size_t)bl * HW + hw0) * Cc);
    float4 z = make_float4(0.f, 0.f, 0.f, 0.f);
#pragma unroll
    for (int k = 0; k < 8; k++)
        fz[tid + k * 256] = z;
    if (tid < 32)
        g_att[(size_t)b * HW + hw0 + tid] = 0.f;
}

// ---------------------------------------------------------------- launch
extern "C" void kernel_launch(void* const* d_in, const int* in_sizes, int n_in,
                              void* d_out, int out_size) {
    const float* x  = (const float*)d_in[0];   // [16,256,128,128]
    const float* cw = (const float*)d_in[1];   // [3,256]
    const float* cb = (const float*)d_in[2];   // [3]
    float* out  = (float*)d_out;                        // [B,C,HW]
    float* offo = out + (size_t)Bs * Cc * HW;           // [B,2,H,W]

    k_pref<<<1, 256>>>(cw, cb);
    for (int b0 = 0; b0 < Bs; b0 += CHUNK) {
        k_scatter<<<dim3(HW / PIX, CHUNK), 256>>>(x, cw, cb, offo, b0);
        k_div<<<dim3(HW / 32, CHUNK), 256>>>(out, b0);
    }
}